// round 3
// baseline (speedup 1.0000x reference)
#include <cuda_runtime.h>
#include <mma.h>
#include <math.h>

using namespace nvcuda;

#define SEQ   4096
#define DIM   512
#define BATCH 2
#define QSCALE 0.044194173824159216f  // 1/sqrt(512)

// ---------------- scratch (device globals; no allocations allowed) ----------
__device__ float g_Q[BATCH * SEQ * DIM];
__device__ float g_K[BATCH * SEQ * DIM];
__device__ float g_V[BATCH * SEQ * DIM];
__device__ float g_AT[BATCH * SEQ * DIM];  // attention output, transposed [b][d][s]

// =============================================================================
// tf32 WMMA GEMM (no bias):  C[m,n] = sum_k A[m,k] * W[n,k]   (unchanged R2)
// =============================================================================
#define TM 128
#define TN 128
#define TK 16
#define SST 24

__device__ __forceinline__ void cp16(void* s, const void* g) {
    unsigned a = (unsigned)__cvta_generic_to_shared(s);
    asm volatile("cp.async.cg.shared.global [%0], [%1], 16;\n" :: "r"(a), "l"(g));
}

__global__ __launch_bounds__(128) void gemm_kernel(
    const float* __restrict__ A,
    const float* __restrict__ W0, const float* __restrict__ W1, const float* __restrict__ W2,
    float* __restrict__ C0, float* __restrict__ C1, float* __restrict__ C2)
{
    const float* W = (blockIdx.z == 0) ? W0 : (blockIdx.z == 1 ? W1 : W2);
    float*       C = (blockIdx.z == 0) ? C0 : (blockIdx.z == 1 ? C1 : C2);

    __shared__ float As[2][TM * SST];
    __shared__ float Bs[2][TN * SST];

    const int tid  = threadIdx.x;
    const int m0   = blockIdx.y * TM;
    const int n0   = blockIdx.x * TN;
    const int warp = tid >> 5;
    const int wr   = warp >> 1;
    const int wc   = warp & 1;

    wmma::fragment<wmma::accumulator, 16, 16, 8, float> c[4][4];
    #pragma unroll
    for (int i = 0; i < 4; i++)
        #pragma unroll
        for (int j = 0; j < 4; j++)
            wmma::fill_fragment(c[i][j], 0.0f);

    auto load_stage = [&](int s, int k0) {
        #pragma unroll
        for (int t = 0; t < 4; t++) {
            int id = tid + t * 128;
            int row = id >> 2, c4 = id & 3;
            cp16(&As[s][row * SST + c4 * 4],
                 &A[(size_t)(m0 + row) * DIM + k0 + c4 * 4]);
        }
        #pragma unroll
        for (int t = 0; t < 4; t++) {
            int id = tid + t * 128;
            int row = id >> 2, c4 = id & 3;
            cp16(&Bs[s][row * SST + c4 * 4],
                 &W[(size_t)(n0 + row) * DIM + k0 + c4 * 4]);
        }
    };

    load_stage(0, 0);
    asm volatile("cp.async.commit_group;\n");

    const int NS = DIM / TK;
    for (int s = 0; s < NS; s++) {
        const int cur = s & 1;
        if (s + 1 < NS) {
            load_stage(cur ^ 1, (s + 1) * TK);
            asm volatile("cp.async.commit_group;\n");
            asm volatile("cp.async.wait_group 1;\n");
        } else {
            asm volatile("cp.async.wait_group 0;\n");
        }
        __syncthreads();

        #pragma unroll
        for (int kk = 0; kk < TK; kk += 8) {
            wmma::fragment<wmma::matrix_a, 16, 16, 8, wmma::precision::tf32, wmma::row_major> a[4];
            wmma::fragment<wmma::matrix_b, 16, 16, 8, wmma::precision::tf32, wmma::col_major> b[4];
            #pragma unroll
            for (int i = 0; i < 4; i++) {
                wmma::load_matrix_sync(a[i], &As[cur][(wr * 64 + i * 16) * SST + kk], SST);
                #pragma unroll
                for (int e = 0; e < a[i].num_elements; e++)
                    a[i].x[e] = wmma::__float_to_tf32(a[i].x[e]);
            }
            #pragma unroll
            for (int j = 0; j < 4; j++) {
                wmma::load_matrix_sync(b[j], &Bs[cur][(wc * 64 + j * 16) * SST + kk], SST);
                #pragma unroll
                for (int e = 0; e < b[j].num_elements; e++)
                    b[j].x[e] = wmma::__float_to_tf32(b[j].x[e]);
            }
            #pragma unroll
            for (int i = 0; i < 4; i++)
                #pragma unroll
                for (int j = 0; j < 4; j++)
                    wmma::mma_sync(c[i][j], a[i], b[j], c[i][j]);
        }
        __syncthreads();
    }

    #pragma unroll
    for (int i = 0; i < 4; i++)
        #pragma unroll
        for (int j = 0; j < 4; j++)
            wmma::store_matrix_sync(
                &C[(size_t)(m0 + wr * 64 + i * 16) * DIM + n0 + wc * 64 + j * 16],
                c[i][j], DIM, wmma::mem_row_major);
}

// =============================================================================
// Query-blocked sparse attention.
// 1 CTA = 64 queries (G=64), 512 threads, key chunks of C=128.
// Warp w owns queries {w, w+16, w+32, w+48}; thread (w,lane) owns dims
// [lane*16, lane*16+16) for those 4 queries: acc[4][16] in registers.
// Per chunk: bitmask scan -> sparse scores -> warp-uniform online softmax
// -> smem-staged PV (16-key batches, swizzled to kill bank conflicts).
// Output written TRANSPOSED AT[b][d][s] via smem transpose (coalesced).
// =============================================================================
#define GQ   64
#define CHK  128
#define NB   16
#define VS_ROW 640   // 512 + swizzle padding (d + 4*(d>>4) max 635)
#define S_LD 129

#define ATTN_SMEM_BYTES (131072 + 33024 + 40960 + 1024 + 512 + 768 + 64)

__global__ __launch_bounds__(512, 1) void attn_kernel(
    const float* __restrict__ Q, const float* __restrict__ K, const float* __restrict__ V,
    const float* __restrict__ mask, const float* __restrict__ bq, const float* __restrict__ bv,
    float* __restrict__ AT)
{
    extern __shared__ char smem_raw[];
    float* Qs = (float*)smem_raw;                                   // 64*512
    float* S  = Qs + GQ * DIM;                                      // 64*129
    float* vs = S  + GQ * S_LD;                                     // 16*640
    unsigned long long* bits = (unsigned long long*)(vs + NB * VS_ROW); // 128
    int*   act  = (int*)(bits + CHK);                               // 128
    float* m_s  = (float*)(act + CHK);                              // 64
    float* l_s  = m_s + GQ;                                         // 64
    float* rs_s = l_s + GQ;                                         // 64
    int*   nact_p = (int*)(rs_s + GQ);

    const int tid  = threadIdx.x;
    const int w    = tid >> 5;
    const int lane = tid & 31;
    const int b    = blockIdx.x >> 6;
    const int q0   = (blockIdx.x & 63) * GQ;

    const unsigned long long gmask = 0x0001000100010001ULL << w;

    // load Q tile (+bq, pre-scaled)
    for (int idx = tid; idx < GQ * DIM; idx += 512) {
        int g = idx >> 9, d = idx & 511;
        Qs[idx] = (Q[((size_t)(b * SEQ) + q0 + g) * DIM + d] + bq[d]) * QSCALE;
    }
    if (tid < GQ) { m_s[tid] = -INFINITY; l_s[tid] = 0.0f; }

    float acc[4][16];
    #pragma unroll
    for (int gi = 0; gi < 4; gi++)
        #pragma unroll
        for (int i = 0; i < 16; i++) acc[gi][i] = 0.0f;

    __syncthreads();

    const float* mbase = mask + ((size_t)(b * SEQ) + q0) * SEQ;
    const float* Kb = K + (size_t)b * SEQ * DIM;
    const float* Vb = V + (size_t)b * SEQ * DIM;

    for (int ch = 0; ch < SEQ / CHK; ++ch) {
        const int base = ch * CHK;

        if (tid < CHK) bits[tid] = 0ULL;
        if (tid == 0) *nact_p = 0;
        __syncthreads();

        // ---- mask scan: 64 rows x 128 cols
        #pragma unroll 4
        for (int r4 = 0; r4 < 16; r4++) {
            int g = r4 * 4 + (tid >> 7);
            int j = tid & 127;
            if (mbase[(size_t)g * SEQ + base + j] > 0.95f)
                atomicOr(&bits[j], 1ULL << g);
        }
        __syncthreads();

        if (tid < CHK && bits[tid]) act[atomicAdd(nact_p, 1)] = tid;
        __syncthreads();
        const int na = *nact_p;
        if (na == 0) { __syncthreads(); continue; }

        // ---- sparse scores: warp per active key
        for (int i = w; i < na; i += 16) {
            int j = act[i];
            const float4* kr = (const float4*)&Kb[(size_t)(base + j) * DIM];
            float4 ka = kr[lane], kb4 = kr[lane + 32], kc = kr[lane + 64], kd = kr[lane + 96];
            unsigned long long wb = bits[j];
            while (wb) {
                int g = __ffsll((long long)wb) - 1;
                wb &= wb - 1;
                const float4* qg = (const float4*)&Qs[g * DIM];
                float4 qa = qg[lane], qb = qg[lane + 32], qc = qg[lane + 64], qd = qg[lane + 96];
                float s = ka.x*qa.x + ka.y*qa.y + ka.z*qa.z + ka.w*qa.w
                        + kb4.x*qb.x + kb4.y*qb.y + kb4.z*qb.z + kb4.w*qb.w
                        + kc.x*qc.x + kc.y*qc.y + kc.z*qc.z + kc.w*qc.w
                        + kd.x*qd.x + kd.y*qd.y + kd.z*qd.z + kd.w*qd.w;
                #pragma unroll
                for (int o = 16; o; o >>= 1) s += __shfl_xor_sync(0xffffffffu, s, o);
                if (lane == 0) S[g * S_LD + j] = s;
            }
        }
        __syncthreads();

        // ---- online softmax phase 1: chunk max per g, compute rescale
        #pragma unroll
        for (int gi = 0; gi < 4; gi++) {
            int g = w + 16 * gi;
            float cm = -INFINITY;
            #pragma unroll
            for (int jj = 0; jj < 4; jj++) {
                int j = lane + jj * 32;
                if ((bits[j] >> g) & 1ULL) cm = fmaxf(cm, S[g * S_LD + j]);
            }
            #pragma unroll
            for (int o = 16; o; o >>= 1) cm = fmaxf(cm, __shfl_xor_sync(0xffffffffu, cm, o));
            if (lane == 0) {
                float mn = fmaxf(m_s[g], cm);
                rs_s[g] = (mn == -INFINITY) ? 1.0f : __expf(m_s[g] - mn);
                m_s[g] = mn;
            }
        }
        __syncthreads();

        // ---- rescale accumulators, exponentiate, chunk sum
        #pragma unroll
        for (int gi = 0; gi < 4; gi++) {
            int g = w + 16 * gi;
            float r = rs_s[g];
            #pragma unroll
            for (int i = 0; i < 16; i++) acc[gi][i] *= r;
            float mg = m_s[g];
            float cs = 0.0f;
            #pragma unroll
            for (int jj = 0; jj < 4; jj++) {
                int j = lane + jj * 32;
                if ((bits[j] >> g) & 1ULL) {
                    float p = __expf(S[g * S_LD + j] - mg);
                    S[g * S_LD + j] = p;
                    cs += p;
                }
            }
            #pragma unroll
            for (int o = 16; o; o >>= 1) cs += __shfl_xor_sync(0xffffffffu, cs, o);
            if (lane == 0) l_s[g] = l_s[g] * r + cs;
        }
        __syncthreads();

        // ---- PV: 16-key staged batches
        for (int ib = 0; ib < na; ib += NB) {
            const int nb = min(NB, na - ib);
            #pragma unroll
            for (int kb = 0; kb < NB; kb++) {
                if (kb < nb) {
                    int j = act[ib + kb];
                    vs[kb * VS_ROW + tid + 4 * (tid >> 4)] =
                        Vb[(size_t)(base + j) * DIM + tid];
                }
            }
            __syncthreads();
            for (int kb = 0; kb < nb; kb++) {
                int j = act[ib + kb];
                unsigned long long wb = bits[j];
                if (wb & gmask) {
                    const float4* vr = (const float4*)&vs[kb * VS_ROW + lane * 20];
                    float4 v0 = vr[0], v1 = vr[1], v2 = vr[2], v3 = vr[3];
                    #pragma unroll
                    for (int gi = 0; gi < 4; gi++) {
                        int g = w + 16 * gi;
                        if ((wb >> g) & 1ULL) {
                            float p = S[g * S_LD + j];
                            acc[gi][0]  += p * v0.x;  acc[gi][1]  += p * v0.y;
                            acc[gi][2]  += p * v0.z;  acc[gi][3]  += p * v0.w;
                            acc[gi][4]  += p * v1.x;  acc[gi][5]  += p * v1.y;
                            acc[gi][6]  += p * v1.z;  acc[gi][7]  += p * v1.w;
                            acc[gi][8]  += p * v2.x;  acc[gi][9]  += p * v2.y;
                            acc[gi][10] += p * v2.z;  acc[gi][11] += p * v2.w;
                            acc[gi][12] += p * v3.x;  acc[gi][13] += p * v3.y;
                            acc[gi][14] += p * v3.z;  acc[gi][15] += p * v3.w;
                        }
                    }
                }
            }
            __syncthreads();
        }
    }

    // ---- output: normalize, +bv, smem transpose, coalesced transposed store
    float invl[4];
    #pragma unroll
    for (int gi = 0; gi < 4; gi++) invl[gi] = 1.0f / l_s[w + 16 * gi];

    for (int r = 0; r < 4; r++) {          // dim mega-rounds of 128
        if ((lane >> 3) == r) {
            #pragma unroll
            for (int gi = 0; gi < 4; gi++) {
                int g = w + 16 * gi;
                #pragma unroll
                for (int i = 0; i < 16; i++) {
                    int d  = lane * 16 + i;
                    int dl = d - 128 * r;
                    S[g * S_LD + dl] = acc[gi][i] * invl[gi] + bv[d];
                }
            }
        }
        __syncthreads();
        #pragma unroll
        for (int k2 = 0; k2 < 16; k2++) {
            int id = tid + 512 * k2;
            int g = id & 63, dd = id >> 6;
            AT[((size_t)(b * DIM) + r * 128 + dd) * SEQ + q0 + g] = S[g * S_LD + dd];
        }
        __syncthreads();
    }
}

// ---------------- final bias add for output projection -----------------------
__global__ __launch_bounds__(256) void add_bias_kernel(
    float* __restrict__ out, const float* __restrict__ bo)
{
    int i = blockIdx.x * 256 + threadIdx.x;
    float4 v = ((float4*)out)[i];
    float4 bb = ((const float4*)bo)[i & 127];
    v.x += bb.x; v.y += bb.y; v.z += bb.z; v.w += bb.w;
    ((float4*)out)[i] = v;
}

// ---------------- launch ------------------------------------------------------
extern "C" void kernel_launch(void* const* d_in, const int* in_sizes, int n_in,
                              void* d_out, int out_size)
{
    const float* x    = (const float*)d_in[0];
    const float* mask = (const float*)d_in[1];
    const float* Wq   = (const float*)d_in[2];
    const float* bq   = (const float*)d_in[3];
    const float* Wk   = (const float*)d_in[4];
    // bk (d_in[5]) unused: softmax is shift-invariant in it
    const float* Wv   = (const float*)d_in[6];
    const float* bv   = (const float*)d_in[7];
    const float* Wo   = (const float*)d_in[8];
    const float* bo   = (const float*)d_in[9];

    float *Q, *K, *V, *AT;
    cudaGetSymbolAddress((void**)&Q,  g_Q);
    cudaGetSymbolAddress((void**)&K,  g_K);
    cudaGetSymbolAddress((void**)&V,  g_V);
    cudaGetSymbolAddress((void**)&AT, g_AT);

    cudaFuncSetAttribute(attn_kernel, cudaFuncAttributeMaxDynamicSharedMemorySize,
                         ATTN_SMEM_BYTES);

    dim3 gq(DIM / TN, (BATCH * SEQ) / TM, 3);
    gemm_kernel<<<gq, 128>>>(x, Wq, Wk, Wv, Q, K, V);

    attn_kernel<<<BATCH * SEQ / GQ, 512, ATTN_SMEM_BYTES>>>(Q, K, V, mask, bq, bv, AT);

    dim3 go(DIM / TN, (BATCH * SEQ) / TM, 1);
    gemm_kernel<<<go, 128>>>(AT, Wo, Wo, Wo,
                             (float*)d_out, (float*)d_out, (float*)d_out);

    add_bias_kernel<<<(BATCH * SEQ * DIM / 4) / 256, 256>>>((float*)d_out, bo);
}

// round 5
// speedup vs baseline: 3.2667x; 3.2667x over previous
#include <cuda_runtime.h>
#include <cuda_fp16.h>
#include <mma.h>
#include <math.h>

using namespace nvcuda;

#define SEQ   4096
#define DIM   512
#define BATCH 2
#define QSCALE 0.044194173824159216f  // 1/sqrt(512)

// ---------------- scratch (device globals; no allocations allowed) ----------
__device__ float g_Q[BATCH * SEQ * DIM];
__device__ float g_K[BATCH * SEQ * DIM];
__device__ float g_V[BATCH * SEQ * DIM];
__device__ float g_AT[BATCH * SEQ * DIM];      // attn out, transposed [b][d][s]
__device__ __half g_Kh[BATCH * SEQ * DIM];     // fp16 K
__device__ __half g_Vh[BATCH * SEQ * DIM];     // fp16 V

// =============================================================================
// tf32 WMMA GEMM (no bias):  C[m,n] = sum_k A[m,k] * W[n,k]   (unchanged)
// =============================================================================
#define TM 128
#define TN 128
#define TK 16
#define SST 24

__device__ __forceinline__ void cp16(void* s, const void* g) {
    unsigned a = (unsigned)__cvta_generic_to_shared(s);
    asm volatile("cp.async.cg.shared.global [%0], [%1], 16;\n" :: "r"(a), "l"(g));
}

__global__ __launch_bounds__(128) void gemm_kernel(
    const float* __restrict__ A,
    const float* __restrict__ W0, const float* __restrict__ W1, const float* __restrict__ W2,
    float* __restrict__ C0, float* __restrict__ C1, float* __restrict__ C2)
{
    const float* W = (blockIdx.z == 0) ? W0 : (blockIdx.z == 1 ? W1 : W2);
    float*       C = (blockIdx.z == 0) ? C0 : (blockIdx.z == 1 ? C1 : C2);

    __shared__ float As[2][TM * SST];
    __shared__ float Bs[2][TN * SST];

    const int tid  = threadIdx.x;
    const int m0   = blockIdx.y * TM;
    const int n0   = blockIdx.x * TN;
    const int warp = tid >> 5;
    const int wr   = warp >> 1;
    const int wc   = warp & 1;

    wmma::fragment<wmma::accumulator, 16, 16, 8, float> c[4][4];
    #pragma unroll
    for (int i = 0; i < 4; i++)
        #pragma unroll
        for (int j = 0; j < 4; j++)
            wmma::fill_fragment(c[i][j], 0.0f);

    auto load_stage = [&](int s, int k0) {
        #pragma unroll
        for (int t = 0; t < 4; t++) {
            int id = tid + t * 128;
            int row = id >> 2, c4 = id & 3;
            cp16(&As[s][row * SST + c4 * 4],
                 &A[(size_t)(m0 + row) * DIM + k0 + c4 * 4]);
        }
        #pragma unroll
        for (int t = 0; t < 4; t++) {
            int id = tid + t * 128;
            int row = id >> 2, c4 = id & 3;
            cp16(&Bs[s][row * SST + c4 * 4],
                 &W[(size_t)(n0 + row) * DIM + k0 + c4 * 4]);
        }
    };

    load_stage(0, 0);
    asm volatile("cp.async.commit_group;\n");

    const int NS = DIM / TK;
    for (int s = 0; s < NS; s++) {
        const int cur = s & 1;
        if (s + 1 < NS) {
            load_stage(cur ^ 1, (s + 1) * TK);
            asm volatile("cp.async.commit_group;\n");
            asm volatile("cp.async.wait_group 1;\n");
        } else {
            asm volatile("cp.async.wait_group 0;\n");
        }
        __syncthreads();

        #pragma unroll
        for (int kk = 0; kk < TK; kk += 8) {
            wmma::fragment<wmma::matrix_a, 16, 16, 8, wmma::precision::tf32, wmma::row_major> a[4];
            wmma::fragment<wmma::matrix_b, 16, 16, 8, wmma::precision::tf32, wmma::col_major> b[4];
            #pragma unroll
            for (int i = 0; i < 4; i++) {
                wmma::load_matrix_sync(a[i], &As[cur][(wr * 64 + i * 16) * SST + kk], SST);
                #pragma unroll
                for (int e = 0; e < a[i].num_elements; e++)
                    a[i].x[e] = wmma::__float_to_tf32(a[i].x[e]);
            }
            #pragma unroll
            for (int j = 0; j < 4; j++) {
                wmma::load_matrix_sync(b[j], &Bs[cur][(wc * 64 + j * 16) * SST + kk], SST);
                #pragma unroll
                for (int e = 0; e < b[j].num_elements; e++)
                    b[j].x[e] = wmma::__float_to_tf32(b[j].x[e]);
            }
            #pragma unroll
            for (int i = 0; i < 4; i++)
                #pragma unroll
                for (int j = 0; j < 4; j++)
                    wmma::mma_sync(c[i][j], a[i], b[j], c[i][j]);
        }
        __syncthreads();
    }

    #pragma unroll
    for (int i = 0; i < 4; i++)
        #pragma unroll
        for (int j = 0; j < 4; j++)
            wmma::store_matrix_sync(
                &C[(size_t)(m0 + wr * 64 + i * 16) * DIM + n0 + wc * 64 + j * 16],
                c[i][j], DIM, wmma::mem_row_major);
}

// ---------------- fp32 -> fp16 convert (K, V) --------------------------------
__global__ __launch_bounds__(256) void convert_h_kernel(
    const float* __restrict__ in, __half* __restrict__ out)
{
    size_t i = ((size_t)blockIdx.x * 256 + threadIdx.x) * 4;
    float4 v = *(const float4*)(in + i);
    __half2 a = __float22half2_rn(make_float2(v.x, v.y));
    __half2 b = __float22half2_rn(make_float2(v.z, v.w));
    uint2 pk;
    pk.x = *(unsigned*)&a;
    pk.y = *(unsigned*)&b;
    *(uint2*)(out + i) = pk;
}

// =============================================================================
// Sparse attention: one CTA (256 threads) per query row, fp16 K/V.
// bq folded into q load; bk dropped (softmax shift-invariant);
// bv folded into output (acc/l + bv since sum(p) = l).
// Output TRANSPOSED AT[b][d][s] == reference transpose(1,2).reshape.
// =============================================================================
#define CHUNK 2048

__global__ __launch_bounds__(256) void attn_kernel(
    const float* __restrict__ Q,
    const __half* __restrict__ K, const __half* __restrict__ V,
    const float* __restrict__ mask, const float* __restrict__ bq,
    const float* __restrict__ bv, float* __restrict__ AT)
{
    __shared__ float qs[DIM];
    __shared__ int   idxs[CHUNK];
    __shared__ float ps[CHUNK];
    __shared__ int   cnt;
    __shared__ float red[8];
    __shared__ float bcast;

    const int tid  = threadIdx.x;
    const int warp = tid >> 5;
    const int lane = tid & 31;
    const int b    = blockIdx.x >> 12;
    const int q    = blockIdx.x & (SEQ - 1);

    // pre-scaled q row (+bq) into smem
    #pragma unroll
    for (int t = 0; t < 2; t++) {
        int d = tid + t * 256;
        qs[d] = (Q[((size_t)b * SEQ + q) * DIM + d] + bq[d]) * QSCALE;
    }

    const float* mrow = mask + ((size_t)b * SEQ + q) * SEQ;
    float m = -INFINITY, l = 0.0f;
    float2 acc = make_float2(0.0f, 0.0f);

    for (int ch = 0; ch < SEQ / CHUNK; ++ch) {
        if (tid == 0) cnt = 0;
        __syncthreads();  // also covers qs visibility on first iter

        const int base = ch * CHUNK;
        #pragma unroll
        for (int j = tid; j < CHUNK; j += 256) {
            if (mrow[base + j] > 0.95f) {
                int p = atomicAdd(&cnt, 1);
                idxs[p] = base + j;
            }
        }
        __syncthreads();
        const int n = cnt;  // uniform

        if (n) {
            // ---- scores: one warp per kept key (fp16 K, 16B per lane-chunk)
            for (int i = warp; i < n; i += 8) {
                const __half* kr = &K[((size_t)b * SEQ + idxs[i]) * DIM];
                float s = 0.0f;
                #pragma unroll
                for (int h = 0; h < 2; h++) {
                    int off = h * 256 + lane * 8;
                    __half2 kk[4];
                    *(uint4*)kk = *(const uint4*)(kr + off);
                    float4 qa = *(const float4*)&qs[off];
                    float4 qb = *(const float4*)&qs[off + 4];
                    float2 k0 = __half22float2(kk[0]);
                    float2 k1 = __half22float2(kk[1]);
                    float2 k2 = __half22float2(kk[2]);
                    float2 k3 = __half22float2(kk[3]);
                    s += k0.x*qa.x + k0.y*qa.y + k1.x*qa.z + k1.y*qa.w
                       + k2.x*qb.x + k2.y*qb.y + k3.x*qb.z + k3.y*qb.w;
                }
                #pragma unroll
                for (int o = 16; o; o >>= 1) s += __shfl_xor_sync(0xffffffffu, s, o);
                if (lane == 0) ps[i] = s;
            }
            __syncthreads();

            // ---- block max
            float cm = -INFINITY;
            for (int i = tid; i < n; i += 256) cm = fmaxf(cm, ps[i]);
            #pragma unroll
            for (int o = 16; o; o >>= 1) cm = fmaxf(cm, __shfl_xor_sync(0xffffffffu, cm, o));
            if (lane == 0) red[warp] = cm;
            __syncthreads();
            if (tid < 32) {
                float v2 = (tid < 8) ? red[tid] : -INFINITY;
                #pragma unroll
                for (int o = 4; o; o >>= 1) v2 = fmaxf(v2, __shfl_xor_sync(0xffffffffu, v2, o));
                if (tid == 0) bcast = v2;
            }
            __syncthreads();

            const float newm = fmaxf(m, bcast);
            const float r    = __expf(m - newm);  // m==-inf -> 0
            acc.x *= r; acc.y *= r; l *= r;
            m = newm;

            // ---- exponentiate + block sum
            float cs = 0.0f;
            for (int i = tid; i < n; i += 256) {
                float p = __expf(ps[i] - m);
                ps[i] = p;
                cs += p;
            }
            #pragma unroll
            for (int o = 16; o; o >>= 1) cs += __shfl_xor_sync(0xffffffffu, cs, o);
            if (lane == 0) red[warp] = cs;
            __syncthreads();
            if (tid < 32) {
                float v2 = (tid < 8) ? red[tid] : 0.0f;
                #pragma unroll
                for (int o = 4; o; o >>= 1) v2 += __shfl_xor_sync(0xffffffffu, v2, o);
                if (tid == 0) bcast = v2;
            }
            __syncthreads();
            l += bcast;

            // ---- PV: thread owns dims (2*tid, 2*tid+1); half2 loads (1KB/key)
            const __half2* Vb2 = (const __half2*)(V + (size_t)b * SEQ * DIM);
            int i = 0;
            for (; i + 3 < n; i += 4) {
                float p0 = ps[i], p1 = ps[i+1], p2 = ps[i+2], p3 = ps[i+3];
                float2 v0 = __half22float2(Vb2[(size_t)idxs[i]   * 256 + tid]);
                float2 v1 = __half22float2(Vb2[(size_t)idxs[i+1] * 256 + tid]);
                float2 v2 = __half22float2(Vb2[(size_t)idxs[i+2] * 256 + tid]);
                float2 v3 = __half22float2(Vb2[(size_t)idxs[i+3] * 256 + tid]);
                acc.x += p0 * v0.x + p1 * v1.x + p2 * v2.x + p3 * v3.x;
                acc.y += p0 * v0.y + p1 * v1.y + p2 * v2.y + p3 * v3.y;
            }
            for (; i < n; i++) {
                float2 vv = __half22float2(Vb2[(size_t)idxs[i] * 256 + tid]);
                acc.x += ps[i] * vv.x;
                acc.y += ps[i] * vv.y;
            }
        }
        __syncthreads();  // protect idxs/ps/cnt reuse next chunk
    }

    const float inv = 1.0f / l;
    const int d0 = 2 * tid, d1 = 2 * tid + 1;
    AT[((size_t)b * DIM + d0) * SEQ + q] = acc.x * inv + bv[d0];
    AT[((size_t)b * DIM + d1) * SEQ + q] = acc.y * inv + bv[d1];
}

// ---------------- final bias add for output projection -----------------------
__global__ __launch_bounds__(256) void add_bias_kernel(
    float* __restrict__ out, const float* __restrict__ bo)
{
    int i = blockIdx.x * 256 + threadIdx.x;
    float4 v = ((float4*)out)[i];
    float4 bb = ((const float4*)bo)[i & 127];
    v.x += bb.x; v.y += bb.y; v.z += bb.z; v.w += bb.w;
    ((float4*)out)[i] = v;
}

// ---------------- launch ------------------------------------------------------
extern "C" void kernel_launch(void* const* d_in, const int* in_sizes, int n_in,
                              void* d_out, int out_size)
{
    const float* x    = (const float*)d_in[0];
    const float* mask = (const float*)d_in[1];
    const float* Wq   = (const float*)d_in[2];
    const float* bq   = (const float*)d_in[3];
    const float* Wk   = (const float*)d_in[4];
    // bk (d_in[5]) unused: softmax is shift-invariant in it
    const float* Wv   = (const float*)d_in[6];
    const float* bv   = (const float*)d_in[7];
    const float* Wo   = (const float*)d_in[8];
    const float* bo   = (const float*)d_in[9];

    float *Q, *K, *V, *AT;
    __half *Kh, *Vh;
    cudaGetSymbolAddress((void**)&Q,  g_Q);
    cudaGetSymbolAddress((void**)&K,  g_K);
    cudaGetSymbolAddress((void**)&V,  g_V);
    cudaGetSymbolAddress((void**)&AT, g_AT);
    cudaGetSymbolAddress((void**)&Kh, g_Kh);
    cudaGetSymbolAddress((void**)&Vh, g_Vh);

    // QKV projections
    dim3 gq(DIM / TN, (BATCH * SEQ) / TM, 3);
    gemm_kernel<<<gq, 128>>>(x, Wq, Wk, Wv, Q, K, V);

    // K, V -> fp16
    const int nconv = (BATCH * SEQ * DIM / 4) / 256;
    convert_h_kernel<<<nconv, 256>>>(K, Kh);
    convert_h_kernel<<<nconv, 256>>>(V, Vh);

    // sparse attention (folds bq, bv), output transposed into AT
    attn_kernel<<<BATCH * SEQ, 256>>>(Q, Kh, Vh, mask, bq, bv, AT);

    // output projection on the (implicitly shuffled) AT buffer
    dim3 go(DIM / TN, (BATCH * SEQ) / TM, 1);
    gemm_kernel<<<go, 128>>>(AT, Wo, Wo, Wo,
                             (float*)d_out, (float*)d_out, (float*)d_out);

    add_bias_kernel<<<(BATCH * SEQ * DIM / 4) / 256, 256>>>((float*)d_out, bo);
}